// round 1
// baseline (speedup 1.0000x reference)
#include <cuda_runtime.h>
#include <math.h>

#define T_TOK 2048
#define H_DIM 1024
#define N1_DIM 2048
#define E_EXP 8
#define NROWS_MAX 4096

// ---------------- device scratch (no allocations allowed) ----------------
__device__ int   g_counts[E_EXP];
__device__ int   g_fill[E_EXP];
__device__ int   g_offsets[E_EXP + 1];
__device__ int   g_rows_token[NROWS_MAX];
__device__ float g_rows_weight[NROWS_MAX];
__device__ int   g_topk_id[NROWS_MAX];
__device__ float g_topk_w[NROWS_MAX];
__device__ float g_act[(size_t)NROWS_MAX * 1024];   // 16 MB activation buffer

// ---------------- kernel 0: zero counters + output ----------------
__global__ void zero_kernel(float* out, int n) {
    int i = blockIdx.x * blockDim.x + threadIdx.x;
    if (i < E_EXP) { g_counts[i] = 0; g_fill[i] = 0; }
    for (int j = i; j < n; j += gridDim.x * blockDim.x) out[j] = 0.f;
}

// ---------------- kernel 1: router (one warp per token) ----------------
__global__ void router_kernel(const float* __restrict__ x,
                              const float* __restrict__ rw,
                              const float* __restrict__ rb,
                              float* __restrict__ ew_out) {
    int gwarp = (blockIdx.x * blockDim.x + threadIdx.x) >> 5;
    int lane  = threadIdx.x & 31;
    if (gwarp >= T_TOK) return;

    const float* xr = x + (size_t)gwarp * H_DIM;
    float xv[32];
#pragma unroll
    for (int j = 0; j < 32; j++) xv[j] = xr[j * 32 + lane];

    float p[E_EXP];
#pragma unroll
    for (int e = 0; e < E_EXP; e++) {
        const float* w = rw + e * H_DIM;
        float s = 0.f;
#pragma unroll
        for (int j = 0; j < 32; j++) s += xv[j] * w[j * 32 + lane];
#pragma unroll
        for (int o = 16; o > 0; o >>= 1) s += __shfl_xor_sync(0xffffffffu, s, o);
        p[e] = s + rb[e];
    }
    // softmax over 8
    float m = p[0];
#pragma unroll
    for (int e = 1; e < E_EXP; e++) m = fmaxf(m, p[e]);
    float sum = 0.f;
#pragma unroll
    for (int e = 0; e < E_EXP; e++) { p[e] = expf(p[e] - m); sum += p[e]; }
    float inv = 1.f / sum;
#pragma unroll
    for (int e = 0; e < E_EXP; e++) p[e] *= inv;

    // top-2, stable tie-break on lower index (matches lax.top_k)
    int i0 = 0;
#pragma unroll
    for (int e = 1; e < E_EXP; e++) if (p[e] > p[i0]) i0 = e;
    int i1 = (i0 == 0) ? 1 : 0;
#pragma unroll
    for (int e = 0; e < E_EXP; e++) if (e != i0 && p[e] > p[i1]) i1 = e;

    if (lane == 0) {
        g_topk_id[gwarp * 2 + 0] = i0;
        g_topk_id[gwarp * 2 + 1] = i1;
        g_topk_w[gwarp * 2 + 0] = p[i0];
        g_topk_w[gwarp * 2 + 1] = p[i1];
        atomicAdd(&g_counts[i0], 1);
        atomicAdd(&g_counts[i1], 1);
        if (ew_out) {
            ew_out[gwarp * 2 + 0] = p[i0];
            ew_out[gwarp * 2 + 1] = p[i1];
        }
    }
}

// ---------------- kernel 2: prefix offsets ----------------
__global__ void offsets_kernel() {
    if (threadIdx.x == 0 && blockIdx.x == 0) {
        int s = 0;
        for (int e = 0; e < E_EXP; e++) { g_offsets[e] = s; s += g_counts[e]; }
        g_offsets[E_EXP] = s;
    }
}

// ---------------- kernel 3: build per-expert row lists ----------------
__global__ void build_kernel() {
    int i = blockIdx.x * blockDim.x + threadIdx.x;
    if (i >= NROWS_MAX) return;
    int e = g_topk_id[i];
    int pos = g_offsets[e] + atomicAdd(&g_fill[e], 1);
    g_rows_token[pos]  = i >> 1;
    g_rows_weight[pos] = g_topk_w[i];
}

// ---------------- kernel 4/5: grouped SGEMM, 128x128x8, 8x8 per thread ----
// IS_G1: A = x gathered by token, epilogue = bias + clamp + GLU -> g_act
// !IS_G1: A = g_act (contiguous rows), epilogue = bias + weighted atomicAdd
template<int N_DIM, bool IS_G1>
__global__ __launch_bounds__(256)
void moe_gemm(const float* __restrict__ A,
              const float* __restrict__ W,
              const float* __restrict__ Wb,
              float* __restrict__ Out) {
    const int e = blockIdx.z;
    const int rowStart = g_offsets[e] + blockIdx.y * 128;
    const int rowEnd   = g_offsets[e + 1];
    if (rowStart >= rowEnd) return;
    const int n0  = blockIdx.x * 128;
    const int tid = threadIdx.x;

    __shared__ float As[2][8][132];   // transposed A tile, padded vs conflicts
    __shared__ float Bs[2][8][128];
    __shared__ int   sRow[128];

    const int rA = tid >> 1;          // 0..127
    const int cA = (tid & 1) * 4;     // 0 or 4
    const int rB = tid >> 5;          // 0..7
    const int cB = (tid & 31) * 4;    // 0..124

    if (tid < 128) {
        int gr = rowStart + tid;
        if (gr >= rowEnd) gr = rowEnd - 1;          // clamp (masked in epilogue)
        sRow[tid] = IS_G1 ? g_rows_token[gr] : gr;  // token idx or global row
    }
    __syncthreads();

    const float* Abase = IS_G1 ? A : (const float*)g_act;
    const float* Arow  = Abase + (size_t)sRow[rA] * 1024 + cA;
    const float* Bp    = W + (size_t)e * 1024 * N_DIM + (size_t)rB * N_DIM + n0 + cB;

    // prologue: tile 0
    float4 a = *(const float4*)(Arow);
    float4 b = *(const float4*)(Bp);
    As[0][cA + 0][rA] = a.x; As[0][cA + 1][rA] = a.y;
    As[0][cA + 2][rA] = a.z; As[0][cA + 3][rA] = a.w;
    *(float4*)&Bs[0][rB][cB] = b;
    __syncthreads();

    const int ty = tid >> 4;   // 0..15 -> row group
    const int tx = tid & 15;   // 0..15 -> col group
    float acc[8][8];
#pragma unroll
    for (int i = 0; i < 8; i++)
#pragma unroll
        for (int j = 0; j < 8; j++) acc[i][j] = 0.f;

    int buf = 0;
    const int NT = 1024 / 8;
    for (int kt = 0; kt < NT; kt++) {
        float4 an, bn;
        if (kt + 1 < NT) {
            an = *(const float4*)(Arow + (kt + 1) * 8);
            bn = *(const float4*)(Bp + (size_t)(kt + 1) * 8 * N_DIM);
        }
#pragma unroll
        for (int k = 0; k < 8; k++) {
            float ar[8], br[8];
            *(float4*)&ar[0] = *(const float4*)&As[buf][k][ty * 8];
            *(float4*)&ar[4] = *(const float4*)&As[buf][k][ty * 8 + 4];
            *(float4*)&br[0] = *(const float4*)&Bs[buf][k][tx * 8];
            *(float4*)&br[4] = *(const float4*)&Bs[buf][k][tx * 8 + 4];
#pragma unroll
            for (int i = 0; i < 8; i++)
#pragma unroll
                for (int j = 0; j < 8; j++)
                    acc[i][j] = fmaf(ar[i], br[j], acc[i][j]);
        }
        if (kt + 1 < NT) {
            int nb = buf ^ 1;
            As[nb][cA + 0][rA] = an.x; As[nb][cA + 1][rA] = an.y;
            As[nb][cA + 2][rA] = an.z; As[nb][cA + 3][rA] = an.w;
            *(float4*)&Bs[nb][rB][cB] = bn;
            __syncthreads();
            buf = nb;
        }
    }

    const float* bias = Wb + (size_t)e * N_DIM;
    const int colBase = n0 + tx * 8;

    if (IS_G1) {
#pragma unroll
        for (int i = 0; i < 8; i++) {
            int gr = rowStart + ty * 8 + i;
            if (gr < rowEnd) {
                float* dst = g_act + (size_t)gr * 1024 + (colBase >> 1);
#pragma unroll
                for (int j = 0; j < 8; j += 2) {
                    float gate = acc[i][j]     + bias[colBase + j];
                    float up   = acc[i][j + 1] + bias[colBase + j + 1];
                    gate = fminf(gate, 7.0f);
                    up   = fminf(fmaxf(up, -7.0f), 7.0f);
                    float glu = gate / (1.0f + expf(-1.702f * gate));
                    dst[j >> 1] = (up + 1.0f) * glu;
                }
            }
        }
    } else {
#pragma unroll
        for (int i = 0; i < 8; i++) {
            int gr = rowStart + ty * 8 + i;
            if (gr < rowEnd) {
                int   token = g_rows_token[gr];
                float wgt   = g_rows_weight[gr];
                float* dst  = Out + (size_t)token * 1024 + colBase;
#pragma unroll
                for (int j = 0; j < 8; j++)
                    atomicAdd(&dst[j], wgt * (acc[i][j] + bias[colBase + j]));
            }
        }
    }
}

// ---------------- launch ----------------
extern "C" void kernel_launch(void* const* d_in, const int* in_sizes, int n_in,
                              void* d_out, int out_size) {
    const float* x   = (const float*)d_in[0];
    const float* rw  = (const float*)d_in[1];
    const float* rb  = (const float*)d_in[2];
    const float* w1  = (const float*)d_in[3];
    const float* w1b = (const float*)d_in[4];
    const float* w2  = (const float*)d_in[5];
    const float* w2b = (const float*)d_in[6];
    float* out = (float*)d_out;

    (void)in_sizes; (void)n_in;

    zero_kernel<<<1024, 256>>>(out, T_TOK * H_DIM);

    float* ew = (out_size >= T_TOK * H_DIM + T_TOK * 2) ? (out + T_TOK * H_DIM)
                                                        : nullptr;
    router_kernel<<<T_TOK / 8, 256>>>(x, rw, rb, ew);
    offsets_kernel<<<1, 32>>>();
    build_kernel<<<NROWS_MAX / 256, 256>>>();

    // GEMM1: [n_e x 1024] @ w1_e[1024 x 2048] -> GLU -> g_act [n_e x 1024]
    moe_gemm<N1_DIM, true><<<dim3(N1_DIM / 128, 32, E_EXP), 256>>>(x, w1, w1b, nullptr);
    // GEMM2: g_act [n_e x 1024] @ w2_e[1024 x 1024] -> weighted scatter-add
    moe_gemm<H_DIM, false><<<dim3(H_DIM / 128, 32, E_EXP), 256>>>(nullptr, w2, w2b, out);
}

// round 3
// speedup vs baseline: 2.8131x; 2.8131x over previous
#include <cuda_runtime.h>
#include <math.h>
#include <stdint.h>

#define T_TOK 2048
#define H_DIM 1024
#define N1_DIM 2048
#define E_EXP 8
#define NROWS_MAX 4096
#define KSTAGE 32
#define NT_STAGES 32   // 1024 / 32

// ---------------- device scratch (no allocations allowed) ----------------
__device__ int   g_counts[E_EXP];
__device__ int   g_fill[E_EXP];
__device__ int   g_offsets[E_EXP + 1];
__device__ int   g_rows_token[NROWS_MAX];
__device__ int   g_rows_slot[NROWS_MAX];
__device__ float g_rows_weight[NROWS_MAX];
__device__ int   g_topk_id[NROWS_MAX];
__device__ float g_topk_w[NROWS_MAX];
__device__ float g_act[(size_t)NROWS_MAX * 1024];      // 16 MB
__device__ float g_y[2][(size_t)T_TOK * 1024];         // 16 MB

// ---------------- helpers ----------------
__device__ __forceinline__ float tf32r(float f) {
    uint32_t u;
    asm("cvt.rna.tf32.f32 %0, %1;" : "=r"(u) : "f"(f));
    return __uint_as_float(u);
}

__device__ __forceinline__ void mma_tf32(float* c, const uint32_t* a, const uint32_t* b) {
    asm volatile(
        "mma.sync.aligned.m16n8k8.row.col.f32.tf32.tf32.f32 "
        "{%0,%1,%2,%3}, {%4,%5,%6,%7}, {%8,%9}, {%0,%1,%2,%3};"
        : "+f"(c[0]), "+f"(c[1]), "+f"(c[2]), "+f"(c[3])
        : "r"(a[0]), "r"(a[1]), "r"(a[2]), "r"(a[3]), "r"(b[0]), "r"(b[1]));
}

// ---------------- kernel 0: zero counters ----------------
__global__ void zero_kernel() {
    int i = threadIdx.x;
    if (i < E_EXP) { g_counts[i] = 0; g_fill[i] = 0; }
}

// ---------------- kernel 1: router (one warp per token) ----------------
__global__ void router_kernel(const float* __restrict__ x,
                              const float* __restrict__ rw,
                              const float* __restrict__ rb,
                              float* __restrict__ ew_out) {
    int gwarp = (blockIdx.x * blockDim.x + threadIdx.x) >> 5;
    int lane  = threadIdx.x & 31;
    if (gwarp >= T_TOK) return;

    const float* xr = x + (size_t)gwarp * H_DIM;
    float xv[32];
#pragma unroll
    for (int j = 0; j < 32; j++) xv[j] = xr[j * 32 + lane];

    float p[E_EXP];
#pragma unroll
    for (int e = 0; e < E_EXP; e++) {
        const float* w = rw + e * H_DIM;
        float s = 0.f;
#pragma unroll
        for (int j = 0; j < 32; j++) s += xv[j] * w[j * 32 + lane];
#pragma unroll
        for (int o = 16; o > 0; o >>= 1) s += __shfl_xor_sync(0xffffffffu, s, o);
        p[e] = s + rb[e];
    }
    float m = p[0];
#pragma unroll
    for (int e = 1; e < E_EXP; e++) m = fmaxf(m, p[e]);
    float sum = 0.f;
#pragma unroll
    for (int e = 0; e < E_EXP; e++) { p[e] = expf(p[e] - m); sum += p[e]; }
    float inv = 1.f / sum;
#pragma unroll
    for (int e = 0; e < E_EXP; e++) p[e] *= inv;

    int i0 = 0;
#pragma unroll
    for (int e = 1; e < E_EXP; e++) if (p[e] > p[i0]) i0 = e;
    int i1 = (i0 == 0) ? 1 : 0;
#pragma unroll
    for (int e = 0; e < E_EXP; e++) if (e != i0 && p[e] > p[i1]) i1 = e;

    if (lane == 0) {
        g_topk_id[gwarp * 2 + 0] = i0;
        g_topk_id[gwarp * 2 + 1] = i1;
        g_topk_w[gwarp * 2 + 0] = p[i0];
        g_topk_w[gwarp * 2 + 1] = p[i1];
        atomicAdd(&g_counts[i0], 1);
        atomicAdd(&g_counts[i1], 1);
        if (ew_out) {
            ew_out[gwarp * 2 + 0] = p[i0];
            ew_out[gwarp * 2 + 1] = p[i1];
        }
    }
}

// ---------------- kernel 2: prefix offsets ----------------
__global__ void offsets_kernel() {
    if (threadIdx.x == 0) {
        int s = 0;
        for (int e = 0; e < E_EXP; e++) { g_offsets[e] = s; s += g_counts[e]; }
        g_offsets[E_EXP] = s;
    }
}

// ---------------- kernel 3: build per-expert row lists ----------------
__global__ void build_kernel() {
    int i = blockIdx.x * blockDim.x + threadIdx.x;
    if (i >= NROWS_MAX) return;
    int e = g_topk_id[i];
    int pos = g_offsets[e] + atomicAdd(&g_fill[e], 1);
    g_rows_token[pos]  = i >> 1;
    g_rows_slot[pos]   = i & 1;
    g_rows_weight[pos] = g_topk_w[i];
}

// ---------------- tf32 mma.sync grouped GEMM ----------------
// CTA tile 128x128, 8 warps in 2x4 grid -> warp tile 64x32.
// A smem: [128 rows][36 floats] (stride 36 -> conflict-free frag loads)
// B smem: [32 k][136 floats]    (stride 136 -> conflict-free frag loads)
#define AS_STRIDE 36
#define BS_STRIDE 136
#define AS_BUF (128 * AS_STRIDE)   // 4608 floats
#define BS_BUF (32 * BS_STRIDE)    // 4352 floats
#define OFF_B_FLT (2 * AS_BUF)     // 9216
#define OFF_ROW_FLT (2 * AS_BUF + 2 * BS_BUF)  // 17920
#define DYN_SMEM ((OFF_ROW_FLT + 128) * 4)     // 72192 bytes

template<int N_DIM, bool IS_G1>
__global__ __launch_bounds__(256)
void moe_gemm_mma(const float* __restrict__ A,
                  const float* __restrict__ W,
                  const float* __restrict__ Wb) {
    const int e = blockIdx.z;
    const int rowStart = g_offsets[e] + blockIdx.y * 128;
    const int rowEnd   = g_offsets[e + 1];
    if (rowStart >= rowEnd) return;
    const int n0  = blockIdx.x * 128;
    const int tid = threadIdx.x;
    const int wid = tid >> 5, lane = tid & 31;

    extern __shared__ float sm[];
    float* smA = sm;
    float* smB = sm + OFF_B_FLT;
    int*   sRow = (int*)(sm + OFF_ROW_FLT);

    if (tid < 128) {
        int gr = rowStart + tid;
        if (gr >= rowEnd) gr = rowEnd - 1;
        sRow[tid] = IS_G1 ? g_rows_token[gr] : gr;
    }
    __syncthreads();

    const float* Ab = IS_G1 ? A : (const float*)g_act;
    const float* Wbase = W + (size_t)e * H_DIM * N_DIM + n0;

    // staging indices
    const int sa_row = tid >> 3;          // +t*32
    const int sa_c4  = (tid & 7) * 4;
    const int sb_k   = tid >> 5;          // +t*8
    const int sb_nf  = (tid & 31) * 4;

    float4 pa[4], pb[4];

#define STAGE_LOAD(KT) do {                                                        \
    int _k0 = (KT) * KSTAGE;                                                       \
    _Pragma("unroll")                                                              \
    for (int t = 0; t < 4; t++) {                                                  \
        pa[t] = *(const float4*)(Ab + (size_t)sRow[sa_row + t * 32] * H_DIM + _k0 + sa_c4); \
        pb[t] = *(const float4*)(Wbase + (size_t)(_k0 + sb_k + t * 8) * N_DIM + sb_nf);     \
    }                                                                              \
} while (0)

#define STAGE_STORE(B) do {                                                        \
    float* _As = smA + (B) * AS_BUF;                                               \
    float* _Bs = smB + (B) * BS_BUF;                                               \
    _Pragma("unroll")                                                              \
    for (int t = 0; t < 4; t++) {                                                  \
        float4 va = pa[t], vb = pb[t];                                             \
        va.x = tf32r(va.x); va.y = tf32r(va.y); va.z = tf32r(va.z); va.w = tf32r(va.w); \
        vb.x = tf32r(vb.x); vb.y = tf32r(vb.y); vb.z = tf32r(vb.z); vb.w = tf32r(vb.w); \
        *(float4*)&_As[(sa_row + t * 32) * AS_STRIDE + sa_c4] = va;                \
        *(float4*)&_Bs[(sb_k + t * 8) * BS_STRIDE + sb_nf]   = vb;                 \
    }                                                                              \
} while (0)

    STAGE_LOAD(0);
    STAGE_STORE(0);
    __syncthreads();

    const int wm0 = (wid >> 2) * 64;
    const int wn0 = (wid & 3) * 32;
    const int g   = lane >> 2;
    const int tg  = lane & 3;

    float acc[4][4][4];
#pragma unroll
    for (int m = 0; m < 4; m++)
#pragma unroll
        for (int n = 0; n < 4; n++)
#pragma unroll
            for (int q = 0; q < 4; q++) acc[m][n][q] = 0.f;

    int buf = 0;
    for (int kt = 0; kt < NT_STAGES; kt++) {
        if (kt + 1 < NT_STAGES) STAGE_LOAD(kt + 1);

        const uint32_t* As = (const uint32_t*)(smA + buf * AS_BUF);
        const uint32_t* Bs = (const uint32_t*)(smB + buf * BS_BUF);
#pragma unroll
        for (int kk = 0; kk < KSTAGE; kk += 8) {
            uint32_t af[4][4], bf[4][2];
#pragma unroll
            for (int m = 0; m < 4; m++) {
                int r0 = (wm0 + m * 16 + g) * AS_STRIDE + kk + tg;
                af[m][0] = As[r0];
                af[m][1] = As[r0 + 8 * AS_STRIDE];
                af[m][2] = As[r0 + 4];
                af[m][3] = As[r0 + 8 * AS_STRIDE + 4];
            }
#pragma unroll
            for (int n = 0; n < 4; n++) {
                int c = wn0 + n * 8 + g;
                bf[n][0] = Bs[(kk + tg) * BS_STRIDE + c];
                bf[n][1] = Bs[(kk + tg + 4) * BS_STRIDE + c];
            }
#pragma unroll
            for (int m = 0; m < 4; m++)
#pragma unroll
                for (int n = 0; n < 4; n++)
                    mma_tf32(acc[m][n], af[m], bf[n]);
        }

        if (kt + 1 < NT_STAGES) {
            STAGE_STORE(buf ^ 1);
            __syncthreads();
            buf ^= 1;
        }
    }

    // ---------------- epilogue ----------------
    const float* bias = Wb + (size_t)e * N_DIM + n0;
#pragma unroll
    for (int m = 0; m < 4; m++) {
#pragma unroll
        for (int half = 0; half < 2; half++) {
            int gr = rowStart + wm0 + m * 16 + g + half * 8;
            if (gr < rowEnd) {
                if (IS_G1) {
                    float* dst = g_act + (size_t)gr * 1024 + (n0 >> 1);
#pragma unroll
                    for (int n = 0; n < 4; n++) {
                        int c = wn0 + n * 8 + tg * 2;
                        float gate = acc[m][n][half * 2 + 0] + bias[c];
                        float up   = acc[m][n][half * 2 + 1] + bias[c + 1];
                        gate = fminf(gate, 7.0f);
                        up   = fminf(fmaxf(up, -7.0f), 7.0f);
                        float glu = gate / (1.0f + expf(-1.702f * gate));
                        dst[c >> 1] = (up + 1.0f) * glu;
                    }
                } else {
                    int   token = g_rows_token[gr];
                    int   slot  = g_rows_slot[gr];
                    float wgt   = g_rows_weight[gr];
                    float* dst  = &g_y[slot][(size_t)token * 1024 + n0];
#pragma unroll
                    for (int n = 0; n < 4; n++) {
                        int c = wn0 + n * 8 + tg * 2;
                        float2 v;
                        v.x = wgt * (acc[m][n][half * 2 + 0] + bias[c]);
                        v.y = wgt * (acc[m][n][half * 2 + 1] + bias[c + 1]);
                        *(float2*)&dst[c] = v;
                    }
                }
            }
        }
    }
}

// ---------------- kernel 6: combine slots ----------------
__global__ void combine_kernel(float* __restrict__ out) {
    const float4* a = (const float4*)&g_y[0][0];
    const float4* b = (const float4*)&g_y[1][0];
    float4* o = (float4*)out;
    int n = T_TOK * 1024 / 4;
    for (int i = blockIdx.x * blockDim.x + threadIdx.x; i < n; i += gridDim.x * blockDim.x) {
        float4 u = a[i], v = b[i];
        o[i] = make_float4(u.x + v.x, u.y + v.y, u.z + v.z, u.w + v.w);
    }
}

// ---------------- launch ----------------
extern "C" void kernel_launch(void* const* d_in, const int* in_sizes, int n_in,
                              void* d_out, int out_size) {
    const float* x   = (const float*)d_in[0];
    const float* rw  = (const float*)d_in[1];
    const float* rb  = (const float*)d_in[2];
    const float* w1  = (const float*)d_in[3];
    const float* w1b = (const float*)d_in[4];
    const float* w2  = (const float*)d_in[5];
    const float* w2b = (const float*)d_in[6];
    float* out = (float*)d_out;
    (void)in_sizes; (void)n_in;

    static int attr_done = 0;
    if (!attr_done) {
        cudaFuncSetAttribute(moe_gemm_mma<N1_DIM, true>,
                             cudaFuncAttributeMaxDynamicSharedMemorySize, DYN_SMEM);
        cudaFuncSetAttribute(moe_gemm_mma<H_DIM, false>,
                             cudaFuncAttributeMaxDynamicSharedMemorySize, DYN_SMEM);
        attr_done = 1;
    }

    zero_kernel<<<1, 32>>>();
    float* ew = (out_size >= T_TOK * H_DIM + T_TOK * 2) ? (out + T_TOK * H_DIM)
                                                        : nullptr;
    router_kernel<<<T_TOK / 8, 256>>>(x, rw, rb, ew);
    offsets_kernel<<<1, 32>>>();
    build_kernel<<<NROWS_MAX / 256, 256>>>();

    moe_gemm_mma<N1_DIM, true><<<dim3(N1_DIM / 128, 32, E_EXP), 256, DYN_SMEM>>>(x, w1, w1b);
    moe_gemm_mma<H_DIM, false><<<dim3(H_DIM / 128, 32, E_EXP), 256, DYN_SMEM>>>(nullptr, w2, w2b);

    combine_kernel<<<512, 256>>>(out);
}

// round 5
// speedup vs baseline: 2.8955x; 1.0293x over previous
#include <cuda_runtime.h>
#include <math.h>
#include <stdint.h>

#define T_TOK 2048
#define H_DIM 1024
#define N1_DIM 2048
#define E_EXP 8
#define NROWS_MAX 4096
#define KSTAGE 32
#define NT_STAGES 32   // 1024 / 32
#define PIPE 3

// ---------------- device scratch (no allocations allowed) ----------------
__device__ int   g_counts[E_EXP];
__device__ int   g_fill[E_EXP];
__device__ int   g_offsets[E_EXP + 1];
__device__ int   g_rows_token[NROWS_MAX];
__device__ int   g_rows_slot[NROWS_MAX];
__device__ float g_rows_weight[NROWS_MAX];
__device__ int   g_topk_id[NROWS_MAX];
__device__ float g_topk_w[NROWS_MAX];
__device__ float g_xr[(size_t)T_TOK * 1024];           // 8 MB  tf32-rounded x
__device__ float g_act[(size_t)NROWS_MAX * 1024];      // 16 MB tf32-rounded act
__device__ float g_y[2][(size_t)T_TOK * 1024];         // 32 MB

// ---------------- helpers ----------------
__device__ __forceinline__ float tf32r(float f) {
    uint32_t u;
    asm("cvt.rna.tf32.f32 %0, %1;" : "=r"(u) : "f"(f));
    return __uint_as_float(u);
}
__device__ __forceinline__ uint32_t tf32b(float f) {
    uint32_t u;
    asm("cvt.rna.tf32.f32 %0, %1;" : "=r"(u) : "f"(f));
    return u;
}
__device__ __forceinline__ uint32_t s2u(const void* p) {
    uint32_t a;
    asm("{ .reg .u64 t; cvta.to.shared.u64 t, %1; cvt.u32.u64 %0, t; }" : "=r"(a) : "l"(p));
    return a;
}
__device__ __forceinline__ void cpa16(uint32_t s, const void* g) {
    asm volatile("cp.async.cg.shared.global [%0], [%1], 16;" :: "r"(s), "l"(g));
}
__device__ __forceinline__ void mma_tf32(float* c, const uint32_t* a, const uint32_t* b) {
    asm volatile(
        "mma.sync.aligned.m16n8k8.row.col.f32.tf32.tf32.f32 "
        "{%0,%1,%2,%3}, {%4,%5,%6,%7}, {%8,%9}, {%0,%1,%2,%3};"
        : "+f"(c[0]), "+f"(c[1]), "+f"(c[2]), "+f"(c[3])
        : "r"(a[0]), "r"(a[1]), "r"(a[2]), "r"(a[3]), "r"(b[0]), "r"(b[1]));
}

// ---------------- kernel 0: zero counters ----------------
__global__ void zero_kernel() {
    int i = threadIdx.x;
    if (i < E_EXP) { g_counts[i] = 0; g_fill[i] = 0; }
}

// ---------------- kernel 1: router (one warp per token) + x tf32 round ----
__global__ void router_kernel(const float* __restrict__ x,
                              const float* __restrict__ rw,
                              const float* __restrict__ rb,
                              float* __restrict__ ew_out) {
    int gwarp = (blockIdx.x * blockDim.x + threadIdx.x) >> 5;
    int lane  = threadIdx.x & 31;
    if (gwarp >= T_TOK) return;

    const float* xr = x + (size_t)gwarp * H_DIM;
    float xv[32];
#pragma unroll
    for (int j = 0; j < 32; j++) xv[j] = xr[j * 32 + lane];

    // rounded copy for the tensor-core path (device-side symbol access)
    float* xo = g_xr + (size_t)gwarp * H_DIM;
#pragma unroll
    for (int j = 0; j < 32; j++) xo[j * 32 + lane] = tf32r(xv[j]);

    float p[E_EXP];
#pragma unroll
    for (int e = 0; e < E_EXP; e++) {
        const float* w = rw + e * H_DIM;
        float s = 0.f;
#pragma unroll
        for (int j = 0; j < 32; j++) s += xv[j] * w[j * 32 + lane];
#pragma unroll
        for (int o = 16; o > 0; o >>= 1) s += __shfl_xor_sync(0xffffffffu, s, o);
        p[e] = s + rb[e];
    }
    float m = p[0];
#pragma unroll
    for (int e = 1; e < E_EXP; e++) m = fmaxf(m, p[e]);
    float sum = 0.f;
#pragma unroll
    for (int e = 0; e < E_EXP; e++) { p[e] = expf(p[e] - m); sum += p[e]; }
    float inv = 1.f / sum;
#pragma unroll
    for (int e = 0; e < E_EXP; e++) p[e] *= inv;

    int i0 = 0;
#pragma unroll
    for (int e = 1; e < E_EXP; e++) if (p[e] > p[i0]) i0 = e;
    int i1 = (i0 == 0) ? 1 : 0;
#pragma unroll
    for (int e = 0; e < E_EXP; e++) if (e != i0 && p[e] > p[i1]) i1 = e;

    if (lane == 0) {
        g_topk_id[gwarp * 2 + 0] = i0;
        g_topk_id[gwarp * 2 + 1] = i1;
        g_topk_w[gwarp * 2 + 0] = p[i0];
        g_topk_w[gwarp * 2 + 1] = p[i1];
        atomicAdd(&g_counts[i0], 1);
        atomicAdd(&g_counts[i1], 1);
        if (ew_out) {
            ew_out[gwarp * 2 + 0] = p[i0];
            ew_out[gwarp * 2 + 1] = p[i1];
        }
    }
}

// ---------------- kernel 2: prefix offsets ----------------
__global__ void offsets_kernel() {
    if (threadIdx.x == 0) {
        int s = 0;
        for (int e = 0; e < E_EXP; e++) { g_offsets[e] = s; s += g_counts[e]; }
        g_offsets[E_EXP] = s;
    }
}

// ---------------- kernel 3: build per-expert row lists ----------------
__global__ void build_kernel() {
    int i = blockIdx.x * blockDim.x + threadIdx.x;
    if (i >= NROWS_MAX) return;
    int e = g_topk_id[i];
    int pos = g_offsets[e] + atomicAdd(&g_fill[e], 1);
    g_rows_token[pos]  = i >> 1;
    g_rows_slot[pos]   = i & 1;
    g_rows_weight[pos] = g_topk_w[i];
}

// ---------------- tf32 mma.sync grouped GEMM, cp.async 3-stage ----------
// CTA tile 128x128, 8 warps in 2x4 grid -> warp tile 64x32.
#define AS_STRIDE 36
#define BS_STRIDE 136
#define AS_BUF (128 * AS_STRIDE)            // 4608 floats
#define BS_BUF (32 * BS_STRIDE)             // 4352 floats
#define STAGE_FLT (AS_BUF + BS_BUF)         // 8960 floats
#define STAGE_BYTES (STAGE_FLT * 4)         // 35840
#define A_BYTES (AS_BUF * 4)                // 18432
#define OFF_ROW_FLT (PIPE * STAGE_FLT)      // 26880
#define DYN_SMEM ((OFF_ROW_FLT + 128) * 4)  // 108032 bytes

template<int N_DIM, bool IS_G1>
__global__ __launch_bounds__(256, 2)
void moe_gemm_mma(const float* __restrict__ W,
                  const float* __restrict__ Wb) {
    const int e = blockIdx.z;
    const int rowStart = g_offsets[e] + blockIdx.y * 128;
    const int rowEnd   = g_offsets[e + 1];
    if (rowStart >= rowEnd) return;
    const int n0  = blockIdx.x * 128;
    const int tid = threadIdx.x;
    const int wid = tid >> 5, lane = tid & 31;

    extern __shared__ float sm[];
    int* sRow = (int*)(sm + OFF_ROW_FLT);
    const uint32_t smem_u = s2u(sm);

    if (tid < 128) {
        int gr = rowStart + tid;
        if (gr >= rowEnd) gr = rowEnd - 1;
        sRow[tid] = IS_G1 ? g_rows_token[gr] : gr;
    }
    __syncthreads();

    // A base chosen DEVICE-side (host cannot take &__device__ symbols)
    const float* Ab = IS_G1 ? (const float*)g_xr : (const float*)g_act;
    const float* Wbase = W + (size_t)e * H_DIM * N_DIM + n0;

    const int sa_row = tid >> 3;          // +t*32
    const int sa_c4  = (tid & 7) * 4;
    const int sb_k   = tid >> 5;          // +t*8
    const int sb_nf  = (tid & 31) * 4;

    const float* aP[4];
#pragma unroll
    for (int t = 0; t < 4; t++)
        aP[t] = Ab + (size_t)sRow[sa_row + t * 32] * H_DIM + sa_c4;

#define ISSUE(KT) do {                                                             \
    if ((KT) < NT_STAGES) {                                                        \
        int _k0 = (KT) * KSTAGE;                                                   \
        uint32_t _sb = smem_u + ((KT) % PIPE) * STAGE_BYTES;                       \
        _Pragma("unroll")                                                          \
        for (int t = 0; t < 4; t++) {                                              \
            cpa16(_sb + ((sa_row + t * 32) * AS_STRIDE + sa_c4) * 4, aP[t] + _k0); \
            cpa16(_sb + A_BYTES + ((sb_k + t * 8) * BS_STRIDE + sb_nf) * 4,        \
                  Wbase + (size_t)(_k0 + sb_k + t * 8) * N_DIM + sb_nf);           \
        }                                                                          \
    }                                                                              \
    asm volatile("cp.async.commit_group;" ::: "memory");                           \
} while (0)

    ISSUE(0);
    ISSUE(1);

    const int wm0 = (wid >> 2) * 64;
    const int wn0 = (wid & 3) * 32;
    const int g   = lane >> 2;
    const int tg  = lane & 3;

    float acc[4][4][4];
#pragma unroll
    for (int m = 0; m < 4; m++)
#pragma unroll
        for (int n = 0; n < 4; n++)
#pragma unroll
            for (int q = 0; q < 4; q++) acc[m][n][q] = 0.f;

    int buf = 0;
    for (int kt = 0; kt < NT_STAGES; kt++) {
        ISSUE(kt + 2);
        asm volatile("cp.async.wait_group 2;" ::: "memory");
        __syncthreads();

        const uint32_t* As = (const uint32_t*)(sm + buf * STAGE_FLT);
        const float*    Bf = sm + buf * STAGE_FLT + AS_BUF;
#pragma unroll
        for (int kk = 0; kk < KSTAGE; kk += 8) {
            uint32_t af[4][4], bf[4][2];
#pragma unroll
            for (int m = 0; m < 4; m++) {
                int r0 = (wm0 + m * 16 + g) * AS_STRIDE + kk + tg;
                af[m][0] = As[r0];
                af[m][1] = As[r0 + 8 * AS_STRIDE];
                af[m][2] = As[r0 + 4];
                af[m][3] = As[r0 + 8 * AS_STRIDE + 4];
            }
#pragma unroll
            for (int n = 0; n < 4; n++) {
                int c = wn0 + n * 8 + g;
                bf[n][0] = tf32b(Bf[(kk + tg) * BS_STRIDE + c]);
                bf[n][1] = tf32b(Bf[(kk + tg + 4) * BS_STRIDE + c]);
            }
#pragma unroll
            for (int m = 0; m < 4; m++)
#pragma unroll
                for (int n = 0; n < 4; n++)
                    mma_tf32(acc[m][n], af[m], bf[n]);
        }
        __syncthreads();
        buf = (buf == PIPE - 1) ? 0 : buf + 1;
    }
#undef ISSUE

    // ---------------- epilogue ----------------
    const float* bias = Wb + (size_t)e * N_DIM + n0;
#pragma unroll
    for (int m = 0; m < 4; m++) {
#pragma unroll
        for (int half = 0; half < 2; half++) {
            int gr = rowStart + wm0 + m * 16 + g + half * 8;
            if (gr < rowEnd) {
                if (IS_G1) {
                    float* dst = g_act + (size_t)gr * 1024 + (n0 >> 1);
#pragma unroll
                    for (int n = 0; n < 4; n++) {
                        int c = wn0 + n * 8 + tg * 2;
                        float gate = acc[m][n][half * 2 + 0] + bias[c];
                        float up   = acc[m][n][half * 2 + 1] + bias[c + 1];
                        gate = fminf(gate, 7.0f);
                        up   = fminf(fmaxf(up, -7.0f), 7.0f);
                        float glu = gate / (1.0f + expf(-1.702f * gate));
                        dst[c >> 1] = tf32r((up + 1.0f) * glu);
                    }
                } else {
                    int   token = g_rows_token[gr];
                    int   slot  = g_rows_slot[gr];
                    float wgt   = g_rows_weight[gr];
                    float* dst  = &g_y[slot][(size_t)token * 1024 + n0];
#pragma unroll
                    for (int n = 0; n < 4; n++) {
                        int c = wn0 + n * 8 + tg * 2;
                        float2 v;
                        v.x = wgt * (acc[m][n][half * 2 + 0] + bias[c]);
                        v.y = wgt * (acc[m][n][half * 2 + 1] + bias[c + 1]);
                        *(float2*)&dst[c] = v;
                    }
                }
            }
        }
    }
}

// ---------------- kernel 6: combine slots ----------------
__global__ void combine_kernel(float* __restrict__ out) {
    const float4* a = (const float4*)&g_y[0][0];
    const float4* b = (const float4*)&g_y[1][0];
    float4* o = (float4*)out;
    int n = T_TOK * 1024 / 4;
    for (int i = blockIdx.x * blockDim.x + threadIdx.x; i < n; i += gridDim.x * blockDim.x) {
        float4 u = a[i], v = b[i];
        o[i] = make_float4(u.x + v.x, u.y + v.y, u.z + v.z, u.w + v.w);
    }
}

// ---------------- launch ----------------
extern "C" void kernel_launch(void* const* d_in, const int* in_sizes, int n_in,
                              void* d_out, int out_size) {
    const float* x   = (const float*)d_in[0];
    const float* rw  = (const float*)d_in[1];
    const float* rb  = (const float*)d_in[2];
    const float* w1  = (const float*)d_in[3];
    const float* w1b = (const float*)d_in[4];
    const float* w2  = (const float*)d_in[5];
    const float* w2b = (const float*)d_in[6];
    float* out = (float*)d_out;
    (void)in_sizes; (void)n_in;

    cudaFuncSetAttribute(moe_gemm_mma<N1_DIM, true>,
                         cudaFuncAttributeMaxDynamicSharedMemorySize, DYN_SMEM);
    cudaFuncSetAttribute(moe_gemm_mma<H_DIM, false>,
                         cudaFuncAttributeMaxDynamicSharedMemorySize, DYN_SMEM);

    zero_kernel<<<1, 32>>>();
    float* ew = (out_size >= T_TOK * H_DIM + T_TOK * 2) ? (out + T_TOK * H_DIM)
                                                        : nullptr;
    router_kernel<<<T_TOK / 8, 256>>>(x, rw, rb, ew);
    offsets_kernel<<<1, 32>>>();
    build_kernel<<<NROWS_MAX / 256, 256>>>();

    moe_gemm_mma<N1_DIM, true><<<dim3(N1_DIM / 128, 32, E_EXP), 256, DYN_SMEM>>>(w1, w1b);
    moe_gemm_mma<H_DIM, false><<<dim3(H_DIM / 128, 32, E_EXP), 256, DYN_SMEM>>>(w2, w2b);

    combine_kernel<<<512, 256>>>(out);
}

// round 6
// speedup vs baseline: 3.4019x; 1.1749x over previous
#include <cuda_runtime.h>
#include <cuda_fp16.h>
#include <math.h>
#include <stdint.h>

#define T_TOK 2048
#define H_DIM 1024
#define N1_DIM 2048
#define E_EXP 8
#define NROWS_MAX 4096
#define KSTAGE 32        // halfs of K per stage
#define NT_STAGES 32     // 1024 / 32
#define PIPE 4

// ---------------- device scratch (no allocations allowed) ----------------
__device__ int    g_counts[E_EXP];
__device__ int    g_fill[E_EXP];
__device__ int    g_offsets[E_EXP + 1];
__device__ int    g_rows_token[NROWS_MAX];
__device__ int    g_rows_slot[NROWS_MAX];
__device__ float  g_rows_weight[NROWS_MAX];
__device__ int    g_topk_id[NROWS_MAX];
__device__ float  g_topk_w[NROWS_MAX];
__device__ __half g_xrh[(size_t)T_TOK * 1024];              // 4 MB  fp16 x
__device__ __half g_acth[(size_t)NROWS_MAX * 1024];         // 8 MB  fp16 act
__device__ __half g_w1h[(size_t)E_EXP * H_DIM * N1_DIM];    // 32 MB fp16 w1
__device__ __half g_w2h[(size_t)E_EXP * H_DIM * H_DIM];     // 16 MB fp16 w2
__device__ float  g_y[2][(size_t)T_TOK * 1024];             // 16 MB

// ---------------- helpers ----------------
__device__ __forceinline__ uint32_t s2u(const void* p) {
    uint32_t a;
    asm("{ .reg .u64 t; cvta.to.shared.u64 t, %1; cvt.u32.u64 %0, t; }" : "=r"(a) : "l"(p));
    return a;
}
__device__ __forceinline__ void cpa16(uint32_t s, const void* g) {
    asm volatile("cp.async.cg.shared.global [%0], [%1], 16;" :: "r"(s), "l"(g));
}
__device__ __forceinline__ void mma_f16(float* c, const uint32_t* a, const uint32_t* b) {
    asm volatile(
        "mma.sync.aligned.m16n8k16.row.col.f32.f16.f16.f32 "
        "{%0,%1,%2,%3}, {%4,%5,%6,%7}, {%8,%9}, {%0,%1,%2,%3};"
        : "+f"(c[0]), "+f"(c[1]), "+f"(c[2]), "+f"(c[3])
        : "r"(a[0]), "r"(a[1]), "r"(a[2]), "r"(a[3]), "r"(b[0]), "r"(b[1]));
}
#define LDSM_X4(r, a)                                                         \
    asm volatile("ldmatrix.sync.aligned.m8n8.x4.shared.b16 {%0,%1,%2,%3},[%4];" \
        : "=r"((r)[0]), "=r"((r)[1]), "=r"((r)[2]), "=r"((r)[3]) : "r"(a))
#define LDSM_X4T(r, a)                                                        \
    asm volatile("ldmatrix.sync.aligned.m8n8.x4.trans.shared.b16 {%0,%1,%2,%3},[%4];" \
        : "=r"((r)[0]), "=r"((r)[1]), "=r"((r)[2]), "=r"((r)[3]) : "r"(a))

// ---------------- kernel 0: zero counters ----------------
__global__ void zero_kernel() {
    int i = threadIdx.x;
    if (i < E_EXP) { g_counts[i] = 0; g_fill[i] = 0; }
}

// ---------------- weight convert f32 -> f16 ----------------
__global__ void cvt_half(const float4* __restrict__ s, int n4, int which) {
    __half2* d = (__half2*)(which ? g_w2h : g_w1h);
    for (int i = blockIdx.x * blockDim.x + threadIdx.x; i < n4; i += gridDim.x * blockDim.x) {
        float4 v = s[i];
        d[2 * i + 0] = __floats2half2_rn(v.x, v.y);
        d[2 * i + 1] = __floats2half2_rn(v.z, v.w);
    }
}

// ---------------- kernel 1: router (one warp per token) + x f16 ----------
__global__ void router_kernel(const float* __restrict__ x,
                              const float* __restrict__ rw,
                              const float* __restrict__ rb,
                              float* __restrict__ ew_out) {
    int gwarp = (blockIdx.x * blockDim.x + threadIdx.x) >> 5;
    int lane  = threadIdx.x & 31;
    if (gwarp >= T_TOK) return;

    const float* xr = x + (size_t)gwarp * H_DIM;
    float xv[32];
#pragma unroll
    for (int j = 0; j < 32; j++) xv[j] = xr[j * 32 + lane];

    __half* xo = g_xrh + (size_t)gwarp * H_DIM;
#pragma unroll
    for (int j = 0; j < 32; j++) xo[j * 32 + lane] = __float2half_rn(xv[j]);

    float p[E_EXP];
#pragma unroll
    for (int e = 0; e < E_EXP; e++) {
        const float* w = rw + e * H_DIM;
        float s = 0.f;
#pragma unroll
        for (int j = 0; j < 32; j++) s += xv[j] * w[j * 32 + lane];
#pragma unroll
        for (int o = 16; o > 0; o >>= 1) s += __shfl_xor_sync(0xffffffffu, s, o);
        p[e] = s + rb[e];
    }
    float m = p[0];
#pragma unroll
    for (int e = 1; e < E_EXP; e++) m = fmaxf(m, p[e]);
    float sum = 0.f;
#pragma unroll
    for (int e = 0; e < E_EXP; e++) { p[e] = expf(p[e] - m); sum += p[e]; }
    float inv = 1.f / sum;
#pragma unroll
    for (int e = 0; e < E_EXP; e++) p[e] *= inv;

    int i0 = 0;
#pragma unroll
    for (int e = 1; e < E_EXP; e++) if (p[e] > p[i0]) i0 = e;
    int i1 = (i0 == 0) ? 1 : 0;
#pragma unroll
    for (int e = 0; e < E_EXP; e++) if (e != i0 && p[e] > p[i1]) i1 = e;

    if (lane == 0) {
        g_topk_id[gwarp * 2 + 0] = i0;
        g_topk_id[gwarp * 2 + 1] = i1;
        g_topk_w[gwarp * 2 + 0] = p[i0];
        g_topk_w[gwarp * 2 + 1] = p[i1];
        atomicAdd(&g_counts[i0], 1);
        atomicAdd(&g_counts[i1], 1);
        if (ew_out) {
            ew_out[gwarp * 2 + 0] = p[i0];
            ew_out[gwarp * 2 + 1] = p[i1];
        }
    }
}

// ---------------- kernel 2: prefix offsets ----------------
__global__ void offsets_kernel() {
    if (threadIdx.x == 0) {
        int s = 0;
        for (int e = 0; e < E_EXP; e++) { g_offsets[e] = s; s += g_counts[e]; }
        g_offsets[E_EXP] = s;
    }
}

// ---------------- kernel 3: build per-expert row lists ----------------
__global__ void build_kernel() {
    int i = blockIdx.x * blockDim.x + threadIdx.x;
    if (i >= NROWS_MAX) return;
    int e = g_topk_id[i];
    int pos = g_offsets[e] + atomicAdd(&g_fill[e], 1);
    g_rows_token[pos]  = i >> 1;
    g_rows_slot[pos]   = i & 1;
    g_rows_weight[pos] = g_topk_w[i];
}

// ---------------- fp16 mma.sync grouped GEMM, cp.async 4-stage ----------
// CTA tile 128x128, 8 warps 2x4 -> warp tile 64x32; K staged 32 halfs.
// A smem [128][40] halfs (80B rows, odd 16B stride), B smem [32][136] halfs.
#define AS_STRIDE 40
#define BS_STRIDE 136
#define A_STG_BYTES (128 * AS_STRIDE * 2)   // 10240
#define B_STG_BYTES (32 * BS_STRIDE * 2)    // 8704
#define STAGE_BYTES (A_STG_BYTES + B_STG_BYTES)  // 18944
#define ROW_OFF (PIPE * STAGE_BYTES)        // 75776
#define DYN_SMEM (ROW_OFF + 512)            // 76288

template<int N_DIM, bool IS_G1>
__global__ __launch_bounds__(256, 2)
void moe_gemm_mma(const float* __restrict__ Wb) {
    const int e = blockIdx.z;
    const int rowStart = g_offsets[e] + blockIdx.y * 128;
    const int rowEnd   = g_offsets[e + 1];
    if (rowStart >= rowEnd) return;
    const int n0  = blockIdx.x * 128;
    const int tid = threadIdx.x;
    const int wid = tid >> 5, lane = tid & 31;

    extern __shared__ char smc[];
    int* sRow = (int*)(smc + ROW_OFF);
    const uint32_t smem_u = s2u(smc);

    if (tid < 128) {
        int gr = rowStart + tid;
        if (gr >= rowEnd) gr = rowEnd - 1;
        sRow[tid] = IS_G1 ? g_rows_token[gr] : gr;
    }
    __syncthreads();

    const __half* Ah = IS_G1 ? (const __half*)g_xrh : (const __half*)g_acth;
    const __half* Wh = (IS_G1 ? (const __half*)g_w1h : (const __half*)g_w2h)
                       + (size_t)e * H_DIM * N_DIM + n0;

    // cp.async staging indices
    const __half* aP = Ah + (size_t)sRow[tid >> 1] * H_DIM + (tid & 1) * 16;
    const int bK = tid >> 3;                  // 0..31
    const int bC = (tid & 7) * 2;             // chunk base 0..14
    const uint32_t sa = smem_u + ((tid >> 1) * AS_STRIDE + (tid & 1) * 16) * 2;
    const uint32_t sb = smem_u + A_STG_BYTES + (bK * BS_STRIDE + bC * 8) * 2;

#define ISSUE(KT) do {                                                             \
    if ((KT) < NT_STAGES) {                                                        \
        int _k0 = (KT) * KSTAGE;                                                   \
        uint32_t _so = ((KT) % PIPE) * STAGE_BYTES;                                \
        _Pragma("unroll")                                                          \
        for (int t = 0; t < 2; t++) {                                              \
            cpa16(sa + _so + t * 16, aP + _k0 + t * 8);                            \
            cpa16(sb + _so + t * 16,                                               \
                  Wh + (size_t)(_k0 + bK) * N_DIM + (bC + t) * 8);                 \
        }                                                                          \
    }                                                                              \
    asm volatile("cp.async.commit_group;" ::: "memory");                           \
} while (0)

    ISSUE(0); ISSUE(1); ISSUE(2);

    const int wm0 = (wid >> 2) * 64;
    const int wn0 = (wid & 3) * 32;
    const int g   = lane >> 2;
    const int tg  = lane & 3;

    // ldmatrix per-lane address pieces
    const int a_rl   = lane & 15;
    const int a_koff = (lane >> 4) * 8;
    const int b_k    = (lane & 7) + ((lane >> 3) & 1) * 8;
    const int b_n    = (lane >> 4) * 8;
    const uint32_t aBase = smem_u + ((wm0 + a_rl) * AS_STRIDE + a_koff) * 2;
    const uint32_t bBase = smem_u + A_STG_BYTES + (b_k * BS_STRIDE + wn0 + b_n) * 2;

    float acc[4][4][4];
#pragma unroll
    for (int m = 0; m < 4; m++)
#pragma unroll
        for (int n = 0; n < 4; n++)
#pragma unroll
            for (int q = 0; q < 4; q++) acc[m][n][q] = 0.f;

    int buf = 0;
    for (int kt = 0; kt < NT_STAGES; kt++) {
        ISSUE(kt + 3);
        asm volatile("cp.async.wait_group 3;" ::: "memory");
        __syncthreads();

        const uint32_t so = buf * STAGE_BYTES;
#pragma unroll
        for (int kk = 0; kk < 2; kk++) {            // two K=16 steps
            uint32_t af[4][4], bf[2][4];
#pragma unroll
            for (int m = 0; m < 4; m++)
                LDSM_X4(af[m], aBase + so + m * (16 * AS_STRIDE * 2) + kk * 32);
#pragma unroll
            for (int p = 0; p < 2; p++)
                LDSM_X4T(bf[p], bBase + so + p * 32 + kk * (16 * BS_STRIDE * 2));
#pragma unroll
            for (int m = 0; m < 4; m++)
#pragma unroll
                for (int n = 0; n < 4; n++)
                    mma_f16(acc[m][n], af[m], &bf[n >> 1][(n & 1) * 2]);
        }
        __syncthreads();
        buf = (buf == PIPE - 1) ? 0 : buf + 1;
    }
#undef ISSUE

    // ---------------- epilogue ----------------
    const float* bias = Wb + (size_t)e * N_DIM + n0;
#pragma unroll
    for (int m = 0; m < 4; m++) {
#pragma unroll
        for (int half = 0; half < 2; half++) {
            int gr = rowStart + wm0 + m * 16 + g + half * 8;
            if (gr < rowEnd) {
                if (IS_G1) {
                    __half* dst = g_acth + (size_t)gr * 1024 + (n0 >> 1);
#pragma unroll
                    for (int n = 0; n < 4; n++) {
                        int c = wn0 + n * 8 + tg * 2;
                        float gate = acc[m][n][half * 2 + 0] + bias[c];
                        float up   = acc[m][n][half * 2 + 1] + bias[c + 1];
                        gate = fminf(gate, 7.0f);
                        up   = fminf(fmaxf(up, -7.0f), 7.0f);
                        float glu = gate / (1.0f + expf(-1.702f * gate));
                        dst[c >> 1] = __float2half_rn((up + 1.0f) * glu);
                    }
                } else {
                    int   token = g_rows_token[gr];
                    int   slot  = g_rows_slot[gr];
                    float wgt   = g_rows_weight[gr];
                    float* dst  = &g_y[slot][(size_t)token * 1024 + n0];
#pragma unroll
                    for (int n = 0; n < 4; n++) {
                        int c = wn0 + n * 8 + tg * 2;
                        float2 v;
                        v.x = wgt * (acc[m][n][half * 2 + 0] + bias[c]);
                        v.y = wgt * (acc[m][n][half * 2 + 1] + bias[c + 1]);
                        *(float2*)&dst[c] = v;
                    }
                }
            }
        }
    }
}

// ---------------- kernel 6: combine slots ----------------
__global__ void combine_kernel(float* __restrict__ out) {
    const float4* a = (const float4*)&g_y[0][0];
    const float4* b = (const float4*)&g_y[1][0];
    float4* o = (float4*)out;
    int n = T_TOK * 1024 / 4;
    for (int i = blockIdx.x * blockDim.x + threadIdx.x; i < n; i += gridDim.x * blockDim.x) {
        float4 u = a[i], v = b[i];
        o[i] = make_float4(u.x + v.x, u.y + v.y, u.z + v.z, u.w + v.w);
    }
}

// ---------------- launch ----------------
extern "C" void kernel_launch(void* const* d_in, const int* in_sizes, int n_in,
                              void* d_out, int out_size) {
    const float* x   = (const float*)d_in[0];
    const float* rw  = (const float*)d_in[1];
    const float* rb  = (const float*)d_in[2];
    const float* w1  = (const float*)d_in[3];
    const float* w1b = (const float*)d_in[4];
    const float* w2  = (const float*)d_in[5];
    const float* w2b = (const float*)d_in[6];
    float* out = (float*)d_out;
    (void)in_sizes; (void)n_in;

    cudaFuncSetAttribute(moe_gemm_mma<N1_DIM, true>,
                         cudaFuncAttributeMaxDynamicSharedMemorySize, DYN_SMEM);
    cudaFuncSetAttribute(moe_gemm_mma<H_DIM, false>,
                         cudaFuncAttributeMaxDynamicSharedMemorySize, DYN_SMEM);

    zero_kernel<<<1, 32>>>();
    cvt_half<<<1024, 256>>>((const float4*)w1, E_EXP * H_DIM * N1_DIM / 4, 0);
    cvt_half<<<1024, 256>>>((const float4*)w2, E_EXP * H_DIM * H_DIM / 4, 1);

    float* ew = (out_size >= T_TOK * H_DIM + T_TOK * 2) ? (out + T_TOK * H_DIM)
                                                        : nullptr;
    router_kernel<<<T_TOK / 8, 256>>>(x, rw, rb, ew);
    offsets_kernel<<<1, 32>>>();
    build_kernel<<<NROWS_MAX / 256, 256>>>();

    moe_gemm_mma<N1_DIM, true><<<dim3(N1_DIM / 128, 32, E_EXP), 256, DYN_SMEM>>>(w1b);
    moe_gemm_mma<H_DIM, false><<<dim3(H_DIM / 128, 32, E_EXP), 256, DYN_SMEM>>>(w2b);

    combine_kernel<<<512, 256>>>(out);
}